// round 6
// baseline (speedup 1.0000x reference)
#include <cuda_runtime.h>
#include <cuda_fp16.h>
#include <cstdint>

// ---------------- scratch (device globals: no allocs allowed) ----------------
__device__ __align__(1024) __half g_Xh[16u * 1024u * 1024u];  // x in fp16 (32MB)
__device__ __align__(1024) __half g_Wt[1024u * 1024u];        // sparsified W^T [N,K] fp16

__device__ __forceinline__ uint32_t smem_u32(const void* p) {
    uint32_t a;
    asm("{ .reg .u64 t; cvta.to.shared.u64 t, %1; cvt.u32.u64 %0, t; }" : "=r"(a) : "l"(p));
    return a;
}

#define CP16(dst, src)                                                      \
    asm volatile("cp.async.cg.shared.global [%0], [%1], 16;"                \
        :: "r"(dst), "l"((uint64_t)__cvta_generic_to_global((const void*)(src))) : "memory")
#define CP_COMMIT()  asm volatile("cp.async.commit_group;" ::: "memory")
#define CP_WAIT1()   asm volatile("cp.async.wait_group 1;" ::: "memory")

__device__ __forceinline__ void ldsm_x4(uint32_t& r0, uint32_t& r1,
                                        uint32_t& r2, uint32_t& r3, uint32_t addr) {
    asm volatile("ldmatrix.sync.aligned.m8n8.x4.shared.b16 {%0,%1,%2,%3}, [%4];"
                 : "=r"(r0), "=r"(r1), "=r"(r2), "=r"(r3) : "r"(addr));
}

__device__ __forceinline__ void mma16816(float* d, const uint32_t* a,
                                         uint32_t b0, uint32_t b1) {
    asm volatile(
        "mma.sync.aligned.m16n8k16.row.col.f32.f16.f16.f32 "
        "{%0,%1,%2,%3}, {%4,%5,%6,%7}, {%8,%9}, {%0,%1,%2,%3};"
        : "+f"(d[0]), "+f"(d[1]), "+f"(d[2]), "+f"(d[3])
        : "r"(a[0]), "r"(a[1]), "r"(a[2]), "r"(a[3]), "r"(b0), "r"(b1));
}

// ---------------------------------------------------------------------------
// Kernel 1: 2:4 sparsify (fp16 semantics) + transpose into Wt[N,K]
// ---------------------------------------------------------------------------
__global__ void sparsify24_t_kernel(const float* __restrict__ W,
                                    const float* __restrict__ scale,
                                    __half* __restrict__ Wt, int K, int N) {
    __shared__ __half tile[32][40];
    const int t = threadIdx.x;                 // 256 threads
    const int k0 = blockIdx.x * 32, n0 = blockIdx.y * 32;
    const float s = scale[0];

    const int k = t >> 3, gn = t & 7;          // one 4-group per thread
    float4 v = *reinterpret_cast<const float4*>(W + (size_t)(k0 + k) * N + n0 + gn * 4);
    __half h[4];
    h[0] = __float2half_rn(v.x); h[1] = __float2half_rn(v.y);
    h[2] = __float2half_rn(v.z); h[3] = __float2half_rn(v.w);
    float a[4];
#pragma unroll
    for (int i = 0; i < 4; i++) a[i] = fabsf(__half2float(h[i]));
    int imax = 0;
#pragma unroll
    for (int i = 1; i < 4; i++) if (a[i] > a[imax]) imax = i;
    float th = -1.0f;
#pragma unroll
    for (int i = 0; i < 4; i++) if (i != imax && a[i] > th) th = a[i];
#pragma unroll
    for (int i = 0; i < 4; i++)
        tile[gn * 4 + i][k] = (a[i] >= th) ? __float2half_rn(__half2float(h[i]) * s)
                                           : __half(0.0f);
    __syncthreads();

    const int r = t >> 3, c4 = (t & 7) * 4;    // write [32n x 32k]
    __half o[4];
#pragma unroll
    for (int i = 0; i < 4; i++) o[i] = tile[r][c4 + i];
    *reinterpret_cast<uint2*>(Wt + (size_t)(n0 + r) * K + k0 + c4) =
        *reinterpret_cast<uint2*>(o);
}

// ---------------------------------------------------------------------------
// Kernel 2: x fp32 -> fp16 (2 x float4 per thread for MLP)
// ---------------------------------------------------------------------------
__global__ void convert_x_kernel(const float* __restrict__ X,
                                 __half* __restrict__ Xh, int n4) {
    int i = (blockIdx.x * blockDim.x + threadIdx.x) * 2;
    if (i + 1 >= n4) return;
    float4 v0 = reinterpret_cast<const float4*>(X)[i];
    float4 v1 = reinterpret_cast<const float4*>(X)[i + 1];
    uint4 u;
    __half2 h;
    h = __floats2half2_rn(v0.x, v0.y); u.x = *reinterpret_cast<uint32_t*>(&h);
    h = __floats2half2_rn(v0.z, v0.w); u.y = *reinterpret_cast<uint32_t*>(&h);
    h = __floats2half2_rn(v1.x, v1.y); u.z = *reinterpret_cast<uint32_t*>(&h);
    h = __floats2half2_rn(v1.z, v1.w); u.w = *reinterpret_cast<uint32_t*>(&h);
    reinterpret_cast<uint4*>(Xh)[i >> 1] = u;
}

// ---------------------------------------------------------------------------
// Kernel 3: mma.sync GEMM  out[M,N] = Xh[M,K] @ Wt[N,K]^T + bias
// BM=128, BN=128, BK=64, 3-stage cp.async, 128 threads.
// 4 warps, each computing a 64x64 tile (2m x 2n warp grid).
// ---------------------------------------------------------------------------
#define BM 128
#define BN 128
#define BK 64
#define STAGES 3
#define STAGE_BYTES (BM * 128 + BN * 128)   // A 16KB + B 16KB = 32KB
#define DYN_SMEM (STAGES * STAGE_BYTES)     // 96KB

__device__ __forceinline__ void load_stage(uint32_t sBase,
                                           const __half* Asrc, const __half* Bsrc,
                                           int K, int tid) {
#pragma unroll
    for (int t = 0; t < 8; t++) {             // A: 128 rows x 8 chunks of 16B
        int idx = tid + t * 128;
        int row = idx >> 3, cb = (idx & 7) * 16;
        uint32_t off = (uint32_t)(row * 128 + cb);
        CP16(sBase + (off ^ ((off >> 3) & 0x70)),
             reinterpret_cast<const char*>(Asrc + (size_t)row * K) + cb);
    }
#pragma unroll
    for (int t = 0; t < 8; t++) {             // B: 128 rows x 8 chunks of 16B
        int idx = tid + t * 128;
        int row = idx >> 3, cb = (idx & 7) * 16;
        uint32_t off = (uint32_t)(row * 128 + cb);
        CP16(sBase + BM * 128 + (off ^ ((off >> 3) & 0x70)),
             reinterpret_cast<const char*>(Bsrc + (size_t)row * K) + cb);
    }
    CP_COMMIT();
}

__global__ __launch_bounds__(128, 2)
void gemm_mma_kernel(const __half* __restrict__ Xh, const __half* __restrict__ Wt,
                     const float* __restrict__ bias, float* __restrict__ out,
                     int M, int N, int K) {
    extern __shared__ __align__(1024) unsigned char dsmem[];
    __shared__ float s_bias[BN];

    const int tid = threadIdx.x;
    const int wid = tid >> 5, lane = tid & 31;
    const int wm = wid & 1;                   // m-warp: offset wm*64
    const int wn = wid >> 1;                  // n-warp: offset wn*64
    const int m0 = blockIdx.y * BM;
    const int n0 = blockIdx.x * BN;

    const uint32_t base = smem_u32(dsmem);
    s_bias[tid] = bias[n0 + tid];

    const __half* Abase = Xh + (size_t)m0 * K;
    const __half* Bbase = Wt + (size_t)n0 * K;
    const int NIT = K / BK;                   // 16

    float acc[4][8][4];                       // 128 fp32 accumulators
#pragma unroll
    for (int i = 0; i < 4; i++)
#pragma unroll
        for (int j = 0; j < 8; j++)
#pragma unroll
            for (int q = 0; q < 4; q++) acc[i][j][q] = 0.0f;

    // ldmatrix per-thread address components (rows are 128B, 8-row XOR swizzle)
    const int lrow = lane & 15;
    const uint32_t xr = (uint32_t)((lane & 7) * 16);
    const uint32_t cbHi = (uint32_t)((lane >> 4) * 16);
    const uint32_t aRow = base + (uint32_t)((wm * 64 + lrow) * 128);
    const uint32_t bRow = base + (uint32_t)(BM * 128 + (wn * 64 + lrow) * 128);

    // prologue
    load_stage(base + 0 * STAGE_BYTES, Abase, Bbase, K, tid);
    load_stage(base + 1 * STAGE_BYTES, Abase + BK, Bbase + BK, K, tid);

    for (int it = 0; it < NIT; it++) {
        const uint32_t soff = (uint32_t)((it % STAGES) * STAGE_BYTES);
        CP_WAIT1();
        __syncthreads();   // single barrier: orders stage-ready AND stage-reuse

        // prefetch stage it+2 (cp.async overlaps with compute below)
        if (it + 2 < NIT) {
            load_stage(base + (uint32_t)(((it + 2) % STAGES) * STAGE_BYTES),
                       Abase + (it + 2) * BK, Bbase + (it + 2) * BK, K, tid);
        } else {
            CP_COMMIT();
        }

#pragma unroll
        for (int kk = 0; kk < 4; kk++) {      // 4 x k16 per 64-K chunk
            const uint32_t cb = (uint32_t)(kk * 32) + cbHi;
            uint32_t a[4][4], b[4][4];
#pragma unroll
            for (int mt = 0; mt < 4; mt++)    // A: 64 rows = 4 x m16
                ldsm_x4(a[mt][0], a[mt][1], a[mt][2], a[mt][3],
                        aRow + soff + (uint32_t)(mt * 2048) + (cb ^ xr));
#pragma unroll
            for (int ng = 0; ng < 4; ng++)    // B: 64 cols = 4 x n16
                ldsm_x4(b[ng][0], b[ng][1], b[ng][2], b[ng][3],
                        bRow + soff + (uint32_t)(ng * 2048) + (cb ^ xr));
#pragma unroll
            for (int mt = 0; mt < 4; mt++)
#pragma unroll
                for (int ng = 0; ng < 4; ng++) {
                    mma16816(acc[mt][ng * 2 + 0], a[mt], b[ng][0], b[ng][2]);
                    mma16816(acc[mt][ng * 2 + 1], a[mt], b[ng][1], b[ng][3]);
                }
        }
        // no trailing barrier: next iteration's barrier orders stage reuse
    }

    // epilogue: bias + float2 stores from acc regs
    const int gid = lane >> 2;                // 0..7
    const int qid = lane & 3;                 // 0..3
#pragma unroll
    for (int mt = 0; mt < 4; mt++) {
        const int row0 = m0 + wm * 64 + mt * 16 + gid;
#pragma unroll
        for (int nb = 0; nb < 8; nb++) {
            const int c = wn * 64 + nb * 8 + qid * 2;
            const float b0 = s_bias[c], b1 = s_bias[c + 1];
            float2 v0 = {acc[mt][nb][0] + b0, acc[mt][nb][1] + b1};
            float2 v1 = {acc[mt][nb][2] + b0, acc[mt][nb][3] + b1};
            *reinterpret_cast<float2*>(out + (size_t)row0 * N + n0 + c) = v0;
            *reinterpret_cast<float2*>(out + (size_t)(row0 + 8) * N + n0 + c) = v1;
        }
    }
}

// ---------------------------------------------------------------------------
extern "C" void kernel_launch(void* const* d_in, const int* in_sizes, int n_in,
                              void* d_out, int out_size) {
    const float* x      = (const float*)d_in[0];
    const float* weight = (const float*)d_in[1];
    const float* bias   = (const float*)d_in[2];
    const float* scale  = (const float*)d_in[3];
    float* out = (float*)d_out;

    const int N = in_sizes[2];
    const int K = in_sizes[1] / N;
    const int M = in_sizes[0] / K;

    __half* Xh = nullptr;
    __half* Wt = nullptr;
    cudaGetSymbolAddress((void**)&Xh, g_Xh);
    cudaGetSymbolAddress((void**)&Wt, g_Wt);

    dim3 sg(K / 32, N / 32);
    sparsify24_t_kernel<<<sg, 256>>>(weight, scale, Wt, K, N);

    const int n8 = (M * K) / 8;
    convert_x_kernel<<<(n8 + 255) / 256, 256>>>(x, Xh, (M * K) / 4);

    cudaFuncSetAttribute(gemm_mma_kernel,
                         cudaFuncAttributeMaxDynamicSharedMemorySize, DYN_SMEM);
    dim3 grid(N / BN, M / BM);
    gemm_mma_kernel<<<grid, 128, DYN_SMEM>>>(Xh, Wt, bias, out, M, N, K);
}

// round 7
// speedup vs baseline: 1.0864x; 1.0864x over previous
#include <cuda_runtime.h>
#include <cuda_fp16.h>
#include <cstdint>

// ---------------- scratch (device globals: no allocs allowed) ----------------
__device__ __align__(1024) __half g_Xh[16u * 1024u * 1024u];  // x in fp16 (32MB)
__device__ __align__(1024) __half g_Wt[1024u * 1024u];        // sparsified W^T [N,K] fp16

__device__ __forceinline__ uint32_t smem_u32(const void* p) {
    uint32_t a;
    asm("{ .reg .u64 t; cvta.to.shared.u64 t, %1; cvt.u32.u64 %0, t; }" : "=r"(a) : "l"(p));
    return a;
}

#define CP16(dst, src)                                                      \
    asm volatile("cp.async.cg.shared.global [%0], [%1], 16;"                \
        :: "r"(dst), "l"((uint64_t)__cvta_generic_to_global((const void*)(src))) : "memory")
#define CP_COMMIT()  asm volatile("cp.async.commit_group;" ::: "memory")
#define CP_WAIT1()   asm volatile("cp.async.wait_group 1;" ::: "memory")

__device__ __forceinline__ void ldsm_x4(uint32_t& r0, uint32_t& r1,
                                        uint32_t& r2, uint32_t& r3, uint32_t addr) {
    asm volatile("ldmatrix.sync.aligned.m8n8.x4.shared.b16 {%0,%1,%2,%3}, [%4];"
                 : "=r"(r0), "=r"(r1), "=r"(r2), "=r"(r3) : "r"(addr));
}

__device__ __forceinline__ void mma16816(float* d, const uint32_t* a,
                                         uint32_t b0, uint32_t b1) {
    asm volatile(
        "mma.sync.aligned.m16n8k16.row.col.f32.f16.f16.f32 "
        "{%0,%1,%2,%3}, {%4,%5,%6,%7}, {%8,%9}, {%0,%1,%2,%3};"
        : "+f"(d[0]), "+f"(d[1]), "+f"(d[2]), "+f"(d[3])
        : "r"(a[0]), "r"(a[1]), "r"(a[2]), "r"(a[3]), "r"(b0), "r"(b1));
}

// ---------------------------------------------------------------------------
// Fused prepass: blocks [0, nConvBlocks) convert x fp32->fp16,
//                blocks [nConvBlocks, ...) 2:4-sparsify + transpose W.
// The two tasks are independent; fusing them into one launch lets the small
// sparsify task overlap under the HBM-bound convert.
// ---------------------------------------------------------------------------
__global__ void prepass_kernel(const float* __restrict__ X,
                               __half* __restrict__ Xh,
                               const float* __restrict__ W,
                               const float* __restrict__ scale,
                               __half* __restrict__ Wt,
                               int K, int N, int nConvBlocks) {
    const int t = threadIdx.x;                 // 256 threads
    if ((int)blockIdx.x < nConvBlocks) {
        // ---- convert: 2 x float4 per thread ----
        int i = (blockIdx.x * 256 + t) * 2;
        float4 v0 = reinterpret_cast<const float4*>(X)[i];
        float4 v1 = reinterpret_cast<const float4*>(X)[i + 1];
        uint4 u;
        __half2 h;
        h = __floats2half2_rn(v0.x, v0.y); u.x = *reinterpret_cast<uint32_t*>(&h);
        h = __floats2half2_rn(v0.z, v0.w); u.y = *reinterpret_cast<uint32_t*>(&h);
        h = __floats2half2_rn(v1.x, v1.y); u.z = *reinterpret_cast<uint32_t*>(&h);
        h = __floats2half2_rn(v1.z, v1.w); u.w = *reinterpret_cast<uint32_t*>(&h);
        reinterpret_cast<uint4*>(Xh)[i >> 1] = u;
        return;
    }
    // ---- sparsify 2:4 (fp16 semantics) + transpose ----
    __shared__ __half tile[32][40];
    const int sb = (int)blockIdx.x - nConvBlocks;
    const int k0 = (sb % (K / 32)) * 32, n0 = (sb / (K / 32)) * 32;
    const float s = scale[0];

    const int k = t >> 3, gn = t & 7;          // one 4-group per thread
    float4 v = *reinterpret_cast<const float4*>(W + (size_t)(k0 + k) * N + n0 + gn * 4);
    __half h[4];
    h[0] = __float2half_rn(v.x); h[1] = __float2half_rn(v.y);
    h[2] = __float2half_rn(v.z); h[3] = __float2half_rn(v.w);
    float a[4];
#pragma unroll
    for (int i = 0; i < 4; i++) a[i] = fabsf(__half2float(h[i]));
    int imax = 0;
#pragma unroll
    for (int i = 1; i < 4; i++) if (a[i] > a[imax]) imax = i;
    float th = -1.0f;
#pragma unroll
    for (int i = 0; i < 4; i++) if (i != imax && a[i] > th) th = a[i];
#pragma unroll
    for (int i = 0; i < 4; i++)
        tile[gn * 4 + i][k] = (a[i] >= th) ? __float2half_rn(__half2float(h[i]) * s)
                                           : __half(0.0f);
    __syncthreads();

    const int r = t >> 3, c4 = (t & 7) * 4;    // write [32n x 32k]
    __half o[4];
#pragma unroll
    for (int i = 0; i < 4; i++) o[i] = tile[r][c4 + i];
    *reinterpret_cast<uint2*>(Wt + (size_t)(n0 + r) * K + k0 + c4) =
        *reinterpret_cast<uint2*>(o);
}

// ---------------------------------------------------------------------------
// GEMM  out[M,N] = Xh[M,K] @ Wt[N,K]^T + bias
// BM=128, BN=128, BK=64 (128B swizzled rows), 3-stage cp.async, 256 threads.
// 8 warps of 32x64 (4m x 2n). ONE __syncthreads per K-chunk.
// ---------------------------------------------------------------------------
#define BM 128
#define BN 128
#define BK 64
#define STAGES 3
#define STAGE_BYTES (BM * 128 + BN * 128)   // A 16KB + B 16KB = 32KB
#define DYN_SMEM (STAGES * STAGE_BYTES)     // 96KB

__device__ __forceinline__ void load_stage(uint32_t sBase,
                                           const __half* Asrc, const __half* Bsrc,
                                           int K, int tid) {
#pragma unroll
    for (int t = 0; t < 4; t++) {             // A: 128 rows x 8 chunks of 16B
        int idx = tid + t * 256;
        int row = idx >> 3, cb = (idx & 7) * 16;
        uint32_t off = (uint32_t)(row * 128 + cb);
        CP16(sBase + (off ^ ((off >> 3) & 0x70)),
             reinterpret_cast<const char*>(Asrc + (size_t)row * K) + cb);
    }
#pragma unroll
    for (int t = 0; t < 4; t++) {             // B: 128 rows x 8 chunks of 16B
        int idx = tid + t * 256;
        int row = idx >> 3, cb = (idx & 7) * 16;
        uint32_t off = (uint32_t)(row * 128 + cb);
        CP16(sBase + BM * 128 + (off ^ ((off >> 3) & 0x70)),
             reinterpret_cast<const char*>(Bsrc + (size_t)row * K) + cb);
    }
    CP_COMMIT();
}

__global__ __launch_bounds__(256, 2)
void gemm_mma_kernel(const __half* __restrict__ Xh, const __half* __restrict__ Wt,
                     const float* __restrict__ bias, float* __restrict__ out,
                     int M, int N, int K) {
    extern __shared__ __align__(1024) unsigned char dsmem[];
    __shared__ float s_bias[BN];

    const int tid = threadIdx.x;
    const int wid = tid >> 5, lane = tid & 31;
    const int wm = wid & 3;                   // m-warp: offset wm*32
    const int wn = wid >> 2;                  // n-warp: offset wn*64
    const int m0 = blockIdx.y * BM;
    const int n0 = blockIdx.x * BN;

    const uint32_t base = smem_u32(dsmem);
    if (tid < BN) s_bias[tid] = bias[n0 + tid];

    const __half* Abase = Xh + (size_t)m0 * K;
    const __half* Bbase = Wt + (size_t)n0 * K;
    const int NIT = K / BK;                   // 16

    float acc[2][8][4];
#pragma unroll
    for (int i = 0; i < 2; i++)
#pragma unroll
        for (int j = 0; j < 8; j++)
#pragma unroll
            for (int q = 0; q < 4; q++) acc[i][j][q] = 0.0f;

    // ldmatrix per-thread address components (rows are 128B, 8-row XOR swizzle)
    const int lrow = lane & 15;
    const uint32_t xr = (uint32_t)((lane & 7) * 16);
    const uint32_t cbHi = (uint32_t)((lane >> 4) * 16);
    const uint32_t aRow = base + (uint32_t)((wm * 32 + lrow) * 128);
    const uint32_t bRow = base + (uint32_t)(BM * 128 + (wn * 64 + lrow) * 128);

    // prologue
    load_stage(base + 0 * STAGE_BYTES, Abase, Bbase, K, tid);
    load_stage(base + 1 * STAGE_BYTES, Abase + BK, Bbase + BK, K, tid);

    uint32_t soff = 0;                         // rotating stage offset
    uint32_t poff = 2 * STAGE_BYTES;           // prefetch stage offset
    for (int it = 0; it < NIT; it++) {
        CP_WAIT1();
        __syncthreads();   // single barrier: orders stage-ready AND stage-reuse

        // prefetch stage it+2 (cp.async overlaps with compute below)
        if (it + 2 < NIT) {
            load_stage(base + poff,
                       Abase + (it + 2) * BK, Bbase + (it + 2) * BK, K, tid);
        } else {
            CP_COMMIT();
        }

#pragma unroll
        for (int kk = 0; kk < 4; kk++) {      // 4 x k16 per 64-K chunk
            const uint32_t cb = (uint32_t)(kk * 32) + cbHi;
            uint32_t a[2][4], b[4][4];
#pragma unroll
            for (int mt = 0; mt < 2; mt++)
                ldsm_x4(a[mt][0], a[mt][1], a[mt][2], a[mt][3],
                        aRow + soff + (uint32_t)(mt * 2048) + (cb ^ xr));
#pragma unroll
            for (int ng = 0; ng < 4; ng++)
                ldsm_x4(b[ng][0], b[ng][1], b[ng][2], b[ng][3],
                        bRow + soff + (uint32_t)(ng * 2048) + (cb ^ xr));
#pragma unroll
            for (int mt = 0; mt < 2; mt++)
#pragma unroll
                for (int ng = 0; ng < 4; ng++) {
                    mma16816(acc[mt][ng * 2 + 0], a[mt], b[ng][0], b[ng][2]);
                    mma16816(acc[mt][ng * 2 + 1], a[mt], b[ng][1], b[ng][3]);
                }
        }
        soff += STAGE_BYTES; if (soff == STAGES * STAGE_BYTES) soff = 0;
        poff += STAGE_BYTES; if (poff == STAGES * STAGE_BYTES) poff = 0;
        // no trailing barrier: next iteration's barrier orders stage reuse
    }

    // epilogue: bias + float2 stores from acc regs
    const int gid = lane >> 2;                // 0..7
    const int qid = lane & 3;                 // 0..3
#pragma unroll
    for (int mt = 0; mt < 2; mt++) {
        const int row0 = m0 + wm * 32 + mt * 16 + gid;
#pragma unroll
        for (int nb = 0; nb < 8; nb++) {
            const int c = wn * 64 + nb * 8 + qid * 2;
            const float b0 = s_bias[c], b1 = s_bias[c + 1];
            float2 v0 = {acc[mt][nb][0] + b0, acc[mt][nb][1] + b1};
            float2 v1 = {acc[mt][nb][2] + b0, acc[mt][nb][3] + b1};
            *reinterpret_cast<float2*>(out + (size_t)row0 * N + n0 + c) = v0;
            *reinterpret_cast<float2*>(out + (size_t)(row0 + 8) * N + n0 + c) = v1;
        }
    }
}

// ---------------------------------------------------------------------------
extern "C" void kernel_launch(void* const* d_in, const int* in_sizes, int n_in,
                              void* d_out, int out_size) {
    const float* x      = (const float*)d_in[0];
    const float* weight = (const float*)d_in[1];
    const float* bias   = (const float*)d_in[2];
    const float* scale  = (const float*)d_in[3];
    float* out = (float*)d_out;

    const int N = in_sizes[2];
    const int K = in_sizes[1] / N;
    const int M = in_sizes[0] / K;

    __half* Xh = nullptr;
    __half* Wt = nullptr;
    cudaGetSymbolAddress((void**)&Xh, g_Xh);
    cudaGetSymbolAddress((void**)&Wt, g_Wt);

    // fused prepass: convert blocks + sparsify blocks in one launch
    const int nConvBlocks = (M * K) / (8 * 256);      // 2 float4 per thread
    const int nSparseBlocks = (K / 32) * (N / 32);
    prepass_kernel<<<nConvBlocks + nSparseBlocks, 256>>>(
        x, Xh, weight, scale, Wt, K, N, nConvBlocks);

    cudaFuncSetAttribute(gemm_mma_kernel,
                         cudaFuncAttributeMaxDynamicSharedMemorySize, DYN_SMEM);
    dim3 grid(N / BN, M / BM);
    gemm_mma_kernel<<<grid, 256, DYN_SMEM>>>(Xh, Wt, bias, out, M, N, K);
}